// round 15
// baseline (speedup 1.0000x reference)
#include <cuda_runtime.h>
#include <cuda_fp16.h>
#include <math.h>
#include <stdint.h>

#define BDIM   4
#define TXQ    4096
#define TXFK   256
#define DMODEL 1024
#define DTEXT  768
#define NHEADS 16
#define HDIM   64
#define MQ     (BDIM*TXQ)     // 16384
#define MKV    (BDIM*TXFK)    // 1024
#define DFF    4096
#define ATT_SCALE 0.125f
#define SCALE_LOG2E 0.1803368801111906f   // ATT_SCALE * log2(e)

// ---------------- scratch (device globals) -----------------------------------
__device__ float g_res [(size_t)MQ * DMODEL];
__device__ float g_bkv [2 * DMODEL];

__device__ __half g_xs   [(size_t)MQ  * DMODEL];
__device__ __half g_xfs  [(size_t)MKV * DTEXT];
__device__ __half g_qh   [(size_t)MQ  * DMODEL];
__device__ __half g_kvh  [(size_t)MKV * 2 * DMODEL];
__device__ __half g_attns[(size_t)MQ  * DMODEL];
__device__ __half g_lns  [(size_t)MQ  * DMODEL];
__device__ __half g_hs   [(size_t)MQ  * DFF];
__device__ __half g_wq   [(size_t)DMODEL * DMODEL];
__device__ __half g_wkv  [(size_t)2 * DMODEL * DTEXT];
__device__ __half g_wo   [(size_t)DMODEL * DMODEL];
__device__ __half g_w1   [(size_t)DFF    * DMODEL];
__device__ __half g_w2   [(size_t)DMODEL * DFF];

__device__ __forceinline__ float gelu_exact(float v) {
    return 0.5f * v * (1.0f + erff(v * 0.7071067811865476f));
}

// ---------------- PTX helpers (target-portable, sm_80+) -----------------------
__device__ __forceinline__ uint32_t smem_u32(const void* p) {
    uint32_t a;
    asm("{ .reg .u64 t; cvta.to.shared.u64 t, %1; cvt.u32.u64 %0, t; }"
        : "=r"(a) : "l"(p));
    return a;
}
__device__ __forceinline__ void cp16(uint32_t s, const void* g) {
    asm volatile("cp.async.cg.shared.global [%0], [%1], 16;" :: "r"(s), "l"(g));
}
__device__ __forceinline__ void ldsm4(uint32_t* r, uint32_t a) {
    asm volatile("ldmatrix.sync.aligned.m8n8.x4.shared.b16 {%0,%1,%2,%3}, [%4];"
        : "=r"(r[0]), "=r"(r[1]), "=r"(r[2]), "=r"(r[3]) : "r"(a));
}
__device__ __forceinline__ void ldsm4t(uint32_t* r, uint32_t a) {
    asm volatile("ldmatrix.sync.aligned.m8n8.x4.trans.shared.b16 {%0,%1,%2,%3}, [%4];"
        : "=r"(r[0]), "=r"(r[1]), "=r"(r[2]), "=r"(r[3]) : "r"(a));
}
__device__ __forceinline__ void mma16816(float* c, const uint32_t* a,
                                         uint32_t b0, uint32_t b1) {
    asm volatile(
        "mma.sync.aligned.m16n8k16.row.col.f32.f16.f16.f32 "
        "{%0,%1,%2,%3}, {%4,%5,%6,%7}, {%8,%9}, {%0,%1,%2,%3};"
        : "+f"(c[0]), "+f"(c[1]), "+f"(c[2]), "+f"(c[3])
        : "r"(a[0]), "r"(a[1]), "r"(a[2]), "r"(a[3]), "r"(b0), "r"(b1));
}
__device__ __forceinline__ uint32_t pack_h2(float a, float b) {
    __half2 t = __floats2half2_rn(a, b);
    uint32_t u; memcpy(&u, &t, 4); return u;
}
__device__ __forceinline__ float fexp2(float y) {
    y = fmaxf(y, -80.0f);
    float r = rintf(y);
    float f = y - r;
    float p =          1.3333558e-3f;
    p = fmaf(p, f,     9.6181291e-3f);
    p = fmaf(p, f,     5.5504109e-2f);
    p = fmaf(p, f,     2.4022651e-1f);
    p = fmaf(p, f,     6.9314718e-1f);
    p = fmaf(p, f,     1.0f);
    return __int_as_float(__float_as_int(p) + (((int)r) << 23));
}

// ---------------- pure fp16 HMMA GEMM, templated BN ----------------------------
// C[M,N] = A[M,K] @ B[N,K]^T. BM=128, BN = 128 or 64, BK=64.
// 256 thr = 8 warps: 4(M) x 2(N); warp tile 32 x (BN/2).
// MODE 0: Cf = acc + bias ; MODE 2: fp16(gelu(acc+bias)) ; MODE 3: +res1+res2 ;
// MODE 4: fp16(acc+bias)
#define NSTAGE 3
#define RASTER_G 16

template<int MODE, int BNT>
__global__ void __launch_bounds__(256, 2) mma_gemm(
    int Nn, int Kk,
    const __half* __restrict__ A, const __half* __restrict__ Bw,
    const float* __restrict__ bias,
    const float* __restrict__ res1, const float* __restrict__ res2,
    float* __restrict__ Cf, __half* __restrict__ Cb, int KOUT)
{
    constexpr int NJP = BNT / 32;               // per-warp 16-col groups
    constexpr int STG = 16384 + BNT * 128;      // stage bytes: A 16KB + B
    extern __shared__ char smraw[];
    const uint32_t smb = smem_u32(smraw);

    const int tid = threadIdx.x;
    const int numX = gridDim.x, numY = gridDim.y;
    const int bid = blockIdx.y * numX + blockIdx.x;
    const int strip = RASTER_G * numX;
    const int sIdx = bid / strip;
    const int rIdx = bid % strip;
    const int gRows = (numY - sIdx * RASTER_G) < RASTER_G ? (numY - sIdx * RASTER_G)
                                                          : RASTER_G;
    const int by = sIdx * RASTER_G + (rIdx % gRows);
    const int bx = rIdx / gRows;

    const int w = tid >> 5, lane = tid & 31;
    const int m0w = (w & 3) * 32, n0w = (w >> 2) * (BNT / 2);

    const __half* Abase = A  + (size_t)(by * 128) * Kk;
    const __half* Bbase = Bw + (size_t)(bx * BNT) * Kk;
    const int nch = Kk >> 6;

    auto load_stage = [&](int c, int s) {
        const uint32_t sa = smb + s * STG;
        const uint32_t sb = sa + 16384;
        const int k0 = c * 64;
#pragma unroll
        for (int i = 0; i < 4; i++) {           // A: 1024 chunks
            int idx = tid + i * 256;
            int row = idx >> 3, cc = idx & 7;
            uint32_t off = row * 128 + ((cc ^ (row & 7)) << 4);
            cp16(sa + off, Abase + (size_t)row * Kk + k0 + cc * 8);
        }
#pragma unroll
        for (int i = 0; i < BNT / 32; i++) {    // B: BNT*8 chunks
            int idx = tid + i * 256;
            int row = idx >> 3, cc = idx & 7;
            uint32_t off = row * 128 + ((cc ^ (row & 7)) << 4);
            cp16(sb + off, Bbase + (size_t)row * Kk + k0 + cc * 8);
        }
        asm volatile("cp.async.commit_group;" ::: "memory");
    };

    float acc[2][2 * NJP][4];
#pragma unroll
    for (int i = 0; i < 2; i++)
#pragma unroll
        for (int j = 0; j < 2 * NJP; j++)
#pragma unroll
            for (int q = 0; q < 4; q++) acc[i][j][q] = 0.0f;

    const int a_row = m0w + (lane & 15);
    const int a_ccb = lane >> 4;
    const int b_row = n0w + (lane & 7) + ((lane >> 4) << 3);
    const int b_ccb = (lane >> 3) & 1;

    load_stage(0, 0);
    if (nch > 1) load_stage(1, 1);

    for (int c = 0; c < nch; c++) {
        const int s = c % NSTAGE;
        if (c + 1 < nch) asm volatile("cp.async.wait_group 1;" ::: "memory");
        else             asm volatile("cp.async.wait_group 0;" ::: "memory");
        __syncthreads();
        if (c + 2 < nch) load_stage(c + 2, (c + 2) % NSTAGE);

        const uint32_t sa = smb + s * STG;
        const uint32_t sb = sa + 16384;
#pragma unroll
        for (int kk = 0; kk < 4; kk++) {
            uint32_t af[2][4];
#pragma unroll
            for (int mi = 0; mi < 2; mi++) {
                int row = a_row + mi * 16;
                int cc = kk * 2 + a_ccb;
                ldsm4(af[mi], sa + row * 128 + ((cc ^ (row & 7)) << 4));
            }
#pragma unroll
            for (int nj = 0; nj < NJP; nj++) {
                uint32_t bf[4];
                int row = b_row + nj * 16;
                int cc = kk * 2 + b_ccb;
                ldsm4(bf, sb + row * 128 + ((cc ^ (row & 7)) << 4));
#pragma unroll
                for (int mi = 0; mi < 2; mi++) {
                    mma16816(acc[mi][nj * 2],     af[mi], bf[0], bf[1]);
                    mma16816(acc[mi][nj * 2 + 1], af[mi], bf[2], bf[3]);
                }
            }
        }
    }

    const int g = lane >> 2, t = lane & 3;
#pragma unroll
    for (int mi = 0; mi < 2; mi++) {
#pragma unroll
        for (int ni = 0; ni < 2 * NJP; ni++) {
            const int col = bx * BNT + n0w + ni * 8 + 2 * t;
            const float b0 = __ldg(bias + col);
            const float b1 = __ldg(bias + col + 1);
            const int row0 = by * 128 + m0w + mi * 16 + g;
#pragma unroll
            for (int h = 0; h < 2; h++) {
                const int row = row0 + h * 8;
                float v0 = acc[mi][ni][2 * h]     + b0;
                float v1 = acc[mi][ni][2 * h + 1] + b1;
                if (MODE == 2) {
                    v0 = gelu_exact(v0); v1 = gelu_exact(v1);
                    *(uint32_t*)(Cb + (size_t)row * KOUT + col) = pack_h2(v0, v1);
                } else if (MODE == 4) {
                    *(uint32_t*)(Cb + (size_t)row * KOUT + col) = pack_h2(v0, v1);
                } else {
                    const size_t base = (size_t)row * Nn + col;
                    if (MODE == 3) {
                        v0 += res1[base]     + res2[base];
                        v1 += res1[base + 1] + res2[base + 1];
                    }
                    *(float2*)(Cf + base) = make_float2(v0, v1);
                }
            }
        }
    }
}

// ---------------- merged prep kernel -------------------------------------------
#define TB_WQ   1024
#define TB_WK   768
#define TB_WV   768
#define TB_WO   1024
#define TB_W1   4096
#define TB_W2   4096
#define CB_X    8192
#define CB_XF   384
#define PREP_BLOCKS (TB_WQ+TB_WK+TB_WV+TB_WO+TB_W1+TB_W2+CB_X+CB_XF+1)

__device__ __forceinline__ void trans_tile(
    const float* __restrict__ W, __half* __restrict__ Y,
    int K, int N, int rowOff, int tileIdx, int tid)
{
    __shared__ float tile[32][33];
    const int nt = N >> 5;
    const int bx = tileIdx % nt, by = tileIdx / nt;
    const int n0 = bx * 32, k0 = by * 32;
    const int tx = tid & 31, ty = tid >> 5;
#pragma unroll
    for (int j = 0; j < 4; j++)
        tile[ty + j * 8][tx] = W[(size_t)(k0 + ty + j * 8) * N + n0 + tx];
    __syncthreads();
#pragma unroll
    for (int j = 0; j < 4; j++)
        Y[(size_t)(rowOff + n0 + ty + j * 8) * K + k0 + tx] =
            __float2half_rn(tile[tx][ty + j * 8]);
}

__device__ __forceinline__ void conv_seg(
    const float* __restrict__ X, __half* __restrict__ Y, int segIdx, int tid)
{
    size_t base = (size_t)segIdx * 2048 + tid * 8;
    float4 a = *(const float4*)(X + base);
    float4 b = *(const float4*)(X + base + 4);
    *(uint4*)(Y + base) = make_uint4(pack_h2(a.x, a.y), pack_h2(a.z, a.w),
                                    pack_h2(b.x, b.y), pack_h2(b.z, b.w));
}

__global__ void __launch_bounds__(256) prep_kernel(
    const float* __restrict__ Wq, const float* __restrict__ Wk,
    const float* __restrict__ Wv, const float* __restrict__ Wo,
    const float* __restrict__ W1, const float* __restrict__ W2,
    const float* __restrict__ x,  const float* __restrict__ xf,
    const float* __restrict__ bk, const float* __restrict__ bv,
    __half* __restrict__ wq, __half* __restrict__ wkv, __half* __restrict__ wo,
    __half* __restrict__ w1, __half* __restrict__ w2,
    __half* __restrict__ xs, __half* __restrict__ xfs, float* __restrict__ bkv)
{
    int b = blockIdx.x;
    const int tid = threadIdx.x;
    if (b < TB_WQ)  { trans_tile(Wq, wq,  DMODEL, DMODEL, 0,      b, tid); return; }
    b -= TB_WQ;
    if (b < TB_WK)  { trans_tile(Wk, wkv, DTEXT,  DMODEL, 0,      b, tid); return; }
    b -= TB_WK;
    if (b < TB_WV)  { trans_tile(Wv, wkv, DTEXT,  DMODEL, DMODEL, b, tid); return; }
    b -= TB_WV;
    if (b < TB_WO)  { trans_tile(Wo, wo,  DMODEL, DMODEL, 0,      b, tid); return; }
    b -= TB_WO;
    if (b < TB_W1)  { trans_tile(W1, w1,  DMODEL, DFF,    0,      b, tid); return; }
    b -= TB_W1;
    if (b < TB_W2)  { trans_tile(W2, w2,  DFF,    DMODEL, 0,      b, tid); return; }
    b -= TB_W2;
    if (b < CB_X)   { conv_seg(x,  xs,  b, tid); return; }
    b -= CB_X;
    if (b < CB_XF)  { conv_seg(xf, xfs, b, tid); return; }
    for (int i = tid; i < DMODEL; i += 256) {
        bkv[i] = bk[i]; bkv[DMODEL + i] = bv[i];
    }
}

// ---------------- HMMA flash-attention (V load overlapped with S chunk 0) ------
#define AQT 128
#define KVW (2 * DMODEL)

__global__ void __launch_bounds__(256, 2) attn_kernel(
    const __half* __restrict__ Qh, const __half* __restrict__ KVh,
    __half* __restrict__ O)
{
    extern __shared__ char smraw[];
    const uint32_t smb = smem_u32(smraw);
    const uint32_t sQ = smb;
    const uint32_t sK = smb + 16384;
    const uint32_t sV = smb + 49152;

    const int bid   = blockIdx.x;
    const int chunk = bid & 31;
    const int h     = (bid >> 5) & 15;
    const int b     = bid >> 9;

    const int tid  = threadIdx.x;
    const int lane = tid & 31;
    const int w    = tid >> 5;

    {
        const __half* qg = Qh + (size_t)(b * TXQ + chunk * AQT) * DMODEL + h * HDIM;
        const __half* kg = KVh + (size_t)(b * TXFK) * KVW + h * HDIM;
        const __half* vg = kg + DMODEL;
        // group 0: Q + K
#pragma unroll
        for (int i = 0; i < 4; i++) {
            int idx = tid + i * 256;
            int row = idx >> 3, cc = idx & 7;
            uint32_t off = row * 128 + ((cc ^ (row & 7)) << 4);
            cp16(sQ + off, qg + (size_t)row * DMODEL + cc * 8);
        }
#pragma unroll
        for (int i = 0; i < 8; i++) {
            int idx = tid + i * 256;
            int row = idx >> 3, cc = idx & 7;
            uint32_t off = row * 128 + ((cc ^ (row & 7)) << 4);
            cp16(sK + off, kg + (size_t)row * KVW + cc * 8);
        }
        asm volatile("cp.async.commit_group;" ::: "memory");
        // group 1: V
#pragma unroll
        for (int i = 0; i < 8; i++) {
            int idx = tid + i * 256;
            int row = idx >> 3, cc = idx & 7;
            uint32_t off = row * 128 + ((cc ^ (row & 7)) << 4);
            cp16(sV + off, vg + (size_t)row * KVW + cc * 8);
        }
        asm volatile("cp.async.commit_group;" ::: "memory");
        asm volatile("cp.async.wait_group 1;" ::: "memory");   // Q + K ready
        __syncthreads();
    }

    uint32_t qf[4][4];
#pragma unroll
    for (int s = 0; s < 4; s++) {
        int row = w * 16 + (lane & 15);
        int cc = 2 * s + (lane >> 4);
        ldsm4(qf[s], sQ + row * 128 + ((cc ^ (row & 7)) << 4));
    }

    float oacc[8][4];
#pragma unroll
    for (int j = 0; j < 8; j++)
#pragma unroll
        for (int q = 0; q < 4; q++) oacc[j][q] = 0.0f;
    float m = -1e30f, l0 = 0.0f, l1 = 0.0f;

    for (int c = 0; c < 4; c++) {
        const int kb = c * 64;
        float sacc[8][4];
#pragma unroll
        for (int j = 0; j < 8; j++)
#pragma unroll
            for (int q = 0; q < 4; q++) sacc[j][q] = 0.0f;

#pragma unroll
        for (int s = 0; s < 4; s++) {
#pragma unroll
            for (int njp = 0; njp < 4; njp++) {
                uint32_t kf[4];
                int row = kb + njp * 16 + (lane & 7) + ((lane >> 4) << 3);
                int cc = 2 * s + ((lane >> 3) & 1);
                ldsm4(kf, sK + row * 128 + ((cc ^ (row & 7)) << 4));
                mma16816(sacc[njp * 2],     qf[s], kf[0], kf[1]);
                mma16816(sacc[njp * 2 + 1], qf[s], kf[2], kf[3]);
            }
        }

        float mx = -1e30f;
#pragma unroll
        for (int j = 0; j < 8; j++) {
            mx = fmaxf(mx, fmaxf(fmaxf(sacc[j][0], sacc[j][1]),
                                 fmaxf(sacc[j][2], sacc[j][3])));
        }
        mx = fmaxf(mx, __shfl_xor_sync(~0u, mx, 1));
        mx = fmaxf(mx, __shfl_xor_sync(~0u, mx, 2));
        float mn = fmaxf(m, mx * SCALE_LOG2E);
        float sc = fexp2(m - mn);
        m = mn;

        float rs0 = 0.0f, rs1 = 0.0f;
#pragma unroll
        for (int j = 0; j < 8; j++) {
            sacc[j][0] = fexp2(fmaf(sacc[j][0], SCALE_LOG2E, -m));
            sacc[j][1] = fexp2(fmaf(sacc[j][1], SCALE_LOG2E, -m));
            sacc[j][2] = fexp2(fmaf(sacc[j][2], SCALE_LOG2E, -m));
            sacc[j][3] = fexp2(fmaf(sacc[j][3], SCALE_LOG2E, -m));
            rs0 += sacc[j][0] + sacc[j][1];
            rs1 += sacc[j][2] + sacc[j][3];
        }
        rs0 += __shfl_xor_sync(~0u, rs0, 1);
        rs0 += __shfl_xor_sync(~0u, rs0, 2);
        rs1 += __shfl_xor_sync(~0u, rs1, 1);
        rs1 += __shfl_xor_sync(~0u, rs1, 2);
        l0 = l0 * sc + rs0;
        l1 = l1 * sc + rs1;
#pragma unroll
        for (int j = 0; j < 8; j++) {
            oacc[j][0] *= sc; oacc[j][1] *= sc;
            oacc[j][2] *= sc; oacc[j][3] *= sc;
        }

        if (c == 0) {   // V becomes needed only now
            asm volatile("cp.async.wait_group 0;" ::: "memory");
            __syncthreads();
        }

#pragma unroll
        for (int t2 = 0; t2 < 4; t2++) {
            uint32_t pf[4];
            pf[0] = pack_h2(sacc[2 * t2][0],     sacc[2 * t2][1]);
            pf[1] = pack_h2(sacc[2 * t2][2],     sacc[2 * t2][3]);
            pf[2] = pack_h2(sacc[2 * t2 + 1][0], sacc[2 * t2 + 1][1]);
            pf[3] = pack_h2(sacc[2 * t2 + 1][2], sacc[2 * t2 + 1][3]);
            const int kk = kb + t2 * 16;
#pragma unroll
            for (int ndp = 0; ndp < 4; ndp++) {
                uint32_t vf[4];
                int row = kk + ((lane >> 3) & 1) * 8 + (lane & 7);
                int cc = 2 * ndp + (lane >> 4);
                ldsm4t(vf, sV + row * 128 + ((cc ^ (row & 7)) << 4));
                mma16816(oacc[ndp * 2],     pf, vf[0], vf[1]);
                mma16816(oacc[ndp * 2 + 1], pf, vf[2], vf[3]);
            }
        }
    }

    const float inv0 = 1.0f / l0, inv1 = 1.0f / l1;
    const int g = lane >> 2, t = lane & 3;
    const size_t row0 = (size_t)(b * TXQ + chunk * AQT + w * 16 + g);
#pragma unroll
    for (int j = 0; j < 8; j++) {
        int col = h * HDIM + j * 8 + 2 * t;
        *(uint32_t*)(O + row0 * DMODEL + col) =
            pack_h2(oacc[j][0] * inv0, oacc[j][1] * inv0);
        *(uint32_t*)(O + (row0 + 8) * DMODEL + col) =
            pack_h2(oacc[j][2] * inv1, oacc[j][3] * inv1);
    }
}

// ---------------- LayerNorm -> fp16 --------------------------------------------
__global__ void __launch_bounds__(256) ln_conv_kernel(
    const float* __restrict__ X, const float* __restrict__ gw,
    const float* __restrict__ bw, __half* __restrict__ Y)
{
    const int row = blockIdx.x;
    const int t = threadIdx.x;
    float4 v = ((const float4*)(X + (size_t)row * DMODEL))[t];
    float s1 = v.x + v.y + v.z + v.w;
    float s2 = v.x * v.x + v.y * v.y + v.z * v.z + v.w * v.w;
#pragma unroll
    for (int o = 16; o; o >>= 1) {
        s1 += __shfl_xor_sync(~0u, s1, o);
        s2 += __shfl_xor_sync(~0u, s2, o);
    }
    __shared__ float r1[8], r2[8];
    const int w = t >> 5, lane = t & 31;
    if (lane == 0) { r1[w] = s1; r2[w] = s2; }
    __syncthreads();
    if (w == 0) {
        s1 = (lane < 8) ? r1[lane] : 0.0f;
        s2 = (lane < 8) ? r2[lane] : 0.0f;
#pragma unroll
        for (int o = 4; o; o >>= 1) {
            s1 += __shfl_xor_sync(~0u, s1, o);
            s2 += __shfl_xor_sync(~0u, s2, o);
        }
        if (lane == 0) { r1[0] = s1; r2[0] = s2; }
    }
    __syncthreads();
    const float mean = r1[0] * (1.0f / DMODEL);
    const float var  = r2[0] * (1.0f / DMODEL) - mean * mean;
    const float rstd = rsqrtf(var + 1e-5f);
    float4 g4 = ((const float4*)gw)[t];
    float4 b4 = ((const float4*)bw)[t];
    float vv[4];
    vv[0] = (v.x - mean) * rstd * g4.x + b4.x;
    vv[1] = (v.y - mean) * rstd * g4.y + b4.y;
    vv[2] = (v.z - mean) * rstd * g4.z + b4.z;
    vv[3] = (v.w - mean) * rstd * g4.w + b4.w;

    *(uint2*)(Y + (size_t)row * DMODEL + t * 4) =
        make_uint2(pack_h2(vv[0], vv[1]), pack_h2(vv[2], vv[3]));
}

// ---------------- launch -------------------------------------------------------
extern "C" void kernel_launch(void* const* d_in, const int* in_sizes, int n_in,
                              void* d_out, int out_size)
{
    const float* x    = (const float*)d_in[0];
    const float* xf   = (const float*)d_in[1];
    const float* Wq   = (const float*)d_in[2];
    const float* bq   = (const float*)d_in[3];
    const float* Wk   = (const float*)d_in[4];
    const float* bk   = (const float*)d_in[5];
    const float* Wv   = (const float*)d_in[6];
    const float* bv   = (const float*)d_in[7];
    const float* Wo   = (const float*)d_in[8];
    const float* bo   = (const float*)d_in[9];
    const float* ln_g = (const float*)d_in[10];
    const float* ln_b = (const float*)d_in[11];
    const float* W1   = (const float*)d_in[12];
    const float* b1   = (const float*)d_in[13];
    const float* W2   = (const float*)d_in[14];
    const float* b2   = (const float*)d_in[15];
    float* out = (float*)d_out;

    float *res, *bkv;
    __half *xs, *xfs, *qh, *kvh, *attns, *lns, *hs, *wq, *wkv, *wo, *w1, *w2;
    cudaGetSymbolAddress((void**)&res,   g_res);
    cudaGetSymbolAddress((void**)&bkv,   g_bkv);
    cudaGetSymbolAddress((void**)&xs,    g_xs);
    cudaGetSymbolAddress((void**)&xfs,   g_xfs);
    cudaGetSymbolAddress((void**)&qh,    g_qh);
    cudaGetSymbolAddress((void**)&kvh,   g_kvh);
    cudaGetSymbolAddress((void**)&attns, g_attns);
    cudaGetSymbolAddress((void**)&lns,   g_lns);
    cudaGetSymbolAddress((void**)&hs,    g_hs);
    cudaGetSymbolAddress((void**)&wq,    g_wq);
    cudaGetSymbolAddress((void**)&wkv,   g_wkv);
    cudaGetSymbolAddress((void**)&wo,    g_wo);
    cudaGetSymbolAddress((void**)&w1,    g_w1);
    cudaGetSymbolAddress((void**)&w2,    g_w2);

    const int SM128 = NSTAGE * (16384 + 128 * 128);   // 96KB
    const int SM64  = NSTAGE * (16384 + 64 * 128);    // 72KB
    cudaFuncSetAttribute((const void*)mma_gemm<4, 64>,  cudaFuncAttributeMaxDynamicSharedMemorySize, SM64);
    cudaFuncSetAttribute((const void*)mma_gemm<0, 64>,  cudaFuncAttributeMaxDynamicSharedMemorySize, SM64);
    cudaFuncSetAttribute((const void*)mma_gemm<3, 64>,  cudaFuncAttributeMaxDynamicSharedMemorySize, SM64);
    cudaFuncSetAttribute((const void*)mma_gemm<4, 128>, cudaFuncAttributeMaxDynamicSharedMemorySize, SM128);
    cudaFuncSetAttribute((const void*)mma_gemm<2, 128>, cudaFuncAttributeMaxDynamicSharedMemorySize, SM128);
    const int ATTN_SMEM = 81920;
    cudaFuncSetAttribute(attn_kernel, cudaFuncAttributeMaxDynamicSharedMemorySize, ATTN_SMEM);

    dim3 blk(256);

    // ONE merged prep launch
    prep_kernel<<<PREP_BLOCKS, blk>>>(Wq, Wk, Wv, Wo, W1, W2, x, xf, bk, bv,
                                      wq, wkv, wo, w1, w2, xs, xfs, bkv);

    // Q projection (BN=64: 2048 tiles, low wave-quantization)
    mma_gemm<4, 64><<<dim3(DMODEL / 64, MQ / 128), blk, SM64>>>(
        DMODEL, DMODEL, xs, wq, bq, nullptr, nullptr, nullptr, qh, DMODEL);
    // fused K|V projection (small; BN=128)
    mma_gemm<4, 128><<<dim3(2 * DMODEL / 128, MKV / 128), blk, SM128>>>(
        2 * DMODEL, DTEXT, xfs, wkv, bkv, nullptr, nullptr, nullptr, kvh, 2 * DMODEL);

    // HMMA flash-attention
    attn_kernel<<<BDIM * NHEADS * (TXQ / AQT), blk, ATTN_SMEM>>>(qh, kvh, attns);

    // out = attn@Wo + bo (BN=64)
    mma_gemm<0, 64><<<dim3(DMODEL / 64, MQ / 128), blk, SM64>>>(
        DMODEL, DMODEL, attns, wo, bo, nullptr, nullptr, res, nullptr, 0);

    // LayerNorm -> fp16
    ln_conv_kernel<<<MQ, blk>>>(res, ln_g, ln_b, lns);

    // h = GELU(ln@W1 + b1) (BN=128: already 4096 tiles)
    mma_gemm<2, 128><<<dim3(DFF / 128, MQ / 128), blk, SM128>>>(
        DFF, DMODEL, lns, w1, b1, nullptr, nullptr, nullptr, hs, DFF);

    // final = h@W2 + b2 + res + x (BN=64)
    mma_gemm<3, 64><<<dim3(DMODEL / 64, MQ / 128), blk, SM64>>>(
        DMODEL, DFF, hs, w2, b2, res, x, out, nullptr, 0);
}

// round 16
// speedup vs baseline: 1.0841x; 1.0841x over previous
#include <cuda_runtime.h>
#include <cuda_fp16.h>
#include <math.h>
#include <stdint.h>

#define BDIM   4
#define TXQ    4096
#define TXFK   256
#define DMODEL 1024
#define DTEXT  768
#define NHEADS 16
#define HDIM   64
#define MQ     (BDIM*TXQ)     // 16384
#define MKV    (BDIM*TXFK)    // 1024
#define DFF    4096
#define ATT_SCALE 0.125f
#define SCALE_LOG2E 0.1803368801111906f

// ---------------- scratch (device globals) -----------------------------------
__device__ float g_res [(size_t)MQ * DMODEL];
__device__ float g_bkv [2 * DMODEL];

__device__ __half g_xs   [(size_t)MQ  * DMODEL];
__device__ __half g_xfs  [(size_t)MKV * DTEXT];
__device__ __half g_qh   [(size_t)MQ  * DMODEL];
__device__ __half g_kvh  [(size_t)MKV * 2 * DMODEL];
__device__ __half g_attns[(size_t)MQ  * DMODEL];
__device__ __half g_lns  [(size_t)MQ  * DMODEL];
__device__ __half g_hs   [(size_t)MQ  * DFF];
__device__ __half g_wq   [(size_t)DMODEL * DMODEL];
__device__ __half g_wkv  [(size_t)2 * DMODEL * DTEXT];
__device__ __half g_wo   [(size_t)DMODEL * DMODEL];
__device__ __half g_w1   [(size_t)DFF    * DMODEL];
__device__ __half g_w2   [(size_t)DMODEL * DFF];

__device__ __forceinline__ float gelu_exact(float v) {
    return 0.5f * v * (1.0f + erff(v * 0.7071067811865476f));
}

// ---------------- PTX helpers (target-portable, sm_80+) -----------------------
__device__ __forceinline__ uint32_t smem_u32(const void* p) {
    uint32_t a;
    asm("{ .reg .u64 t; cvta.to.shared.u64 t, %1; cvt.u32.u64 %0, t; }"
        : "=r"(a) : "l"(p));
    return a;
}
__device__ __forceinline__ void cp16(uint32_t s, const void* g) {
    asm volatile("cp.async.cg.shared.global [%0], [%1], 16;" :: "r"(s), "l"(g));
}
__device__ __forceinline__ void ldsm4(uint32_t* r, uint32_t a) {
    asm volatile("ldmatrix.sync.aligned.m8n8.x4.shared.b16 {%0,%1,%2,%3}, [%4];"
        : "=r"(r[0]), "=r"(r[1]), "=r"(r[2]), "=r"(r[3]) : "r"(a));
}
__device__ __forceinline__ void ldsm4t(uint32_t* r, uint32_t a) {
    asm volatile("ldmatrix.sync.aligned.m8n8.x4.trans.shared.b16 {%0,%1,%2,%3}, [%4];"
        : "=r"(r[0]), "=r"(r[1]), "=r"(r[2]), "=r"(r[3]) : "r"(a));
}
__device__ __forceinline__ void mma16816(float* c, const uint32_t* a,
                                         uint32_t b0, uint32_t b1) {
    asm volatile(
        "mma.sync.aligned.m16n8k16.row.col.f32.f16.f16.f32 "
        "{%0,%1,%2,%3}, {%4,%5,%6,%7}, {%8,%9}, {%0,%1,%2,%3};"
        : "+f"(c[0]), "+f"(c[1]), "+f"(c[2]), "+f"(c[3])
        : "r"(a[0]), "r"(a[1]), "r"(a[2]), "r"(a[3]), "r"(b0), "r"(b1));
}
__device__ __forceinline__ uint32_t pack_h2(float a, float b) {
    __half2 t = __floats2half2_rn(a, b);
    uint32_t u; memcpy(&u, &t, 4); return u;
}
__device__ __forceinline__ float fexp2(float y) {
    y = fmaxf(y, -80.0f);
    float r = rintf(y);
    float f = y - r;
    float p =          1.3333558e-3f;
    p = fmaf(p, f,     9.6181291e-3f);
    p = fmaf(p, f,     5.5504109e-2f);
    p = fmaf(p, f,     2.4022651e-1f);
    p = fmaf(p, f,     6.9314718e-1f);
    p = fmaf(p, f,     1.0f);
    return __int_as_float(__float_as_int(p) + (((int)r) << 23));
}

// ---------------- pure fp16 HMMA GEMM (R14 config: BM=BN=128, BK=64) -----------
#define STAGE_BYTES 32768
#define NSTAGE 3
#define RASTER_G 16

template<int MODE>
__global__ void __launch_bounds__(256, 2) mma_gemm(
    int Nn, int Kk,
    const __half* __restrict__ A, const __half* __restrict__ Bw,
    const float* __restrict__ bias,
    const float* __restrict__ res1, const float* __restrict__ res2,
    float* __restrict__ Cf, __half* __restrict__ Cb, int KOUT)
{
    extern __shared__ char smraw[];
    const uint32_t smb = smem_u32(smraw);

    const int tid = threadIdx.x;
    const int numX = gridDim.x, numY = gridDim.y;
    const int bid = blockIdx.y * numX + blockIdx.x;
    const int strip = RASTER_G * numX;
    const int sIdx = bid / strip;
    const int rIdx = bid % strip;
    const int gRows = (numY - sIdx * RASTER_G) < RASTER_G ? (numY - sIdx * RASTER_G)
                                                          : RASTER_G;
    const int by = sIdx * RASTER_G + (rIdx % gRows);
    const int bx = rIdx / gRows;

    const int w = tid >> 5, lane = tid & 31;
    const int m0w = (w & 3) * 32, n0w = (w >> 2) * 64;

    const __half* Abase = A  + (size_t)(by * 128) * Kk;
    const __half* Bbase = Bw + (size_t)(bx * 128) * Kk;
    const int nch = Kk >> 6;

    auto load_stage = [&](int c, int s) {
        const uint32_t sa = smb + s * STAGE_BYTES;
        const uint32_t sb = sa + 16384;
        const int k0 = c * 64;
#pragma unroll
        for (int i = 0; i < 4; i++) {
            int idx = tid + i * 256;
            int row = idx >> 3, cc = idx & 7;
            uint32_t off = row * 128 + ((cc ^ (row & 7)) << 4);
            cp16(sa + off, Abase + (size_t)row * Kk + k0 + cc * 8);
            cp16(sb + off, Bbase + (size_t)row * Kk + k0 + cc * 8);
        }
        asm volatile("cp.async.commit_group;" ::: "memory");
    };

    float acc[2][8][4];
#pragma unroll
    for (int i = 0; i < 2; i++)
#pragma unroll
        for (int j = 0; j < 8; j++)
#pragma unroll
            for (int q = 0; q < 4; q++) acc[i][j][q] = 0.0f;

    const int a_row = m0w + (lane & 15);
    const int a_ccb = lane >> 4;
    const int b_row = n0w + (lane & 7) + ((lane >> 4) << 3);
    const int b_ccb = (lane >> 3) & 1;

    load_stage(0, 0);
    if (nch > 1) load_stage(1, 1);

    for (int c = 0; c < nch; c++) {
        const int s = c % NSTAGE;
        if (c + 1 < nch) asm volatile("cp.async.wait_group 1;" ::: "memory");
        else             asm volatile("cp.async.wait_group 0;" ::: "memory");
        __syncthreads();
        if (c + 2 < nch) load_stage(c + 2, (c + 2) % NSTAGE);

        const uint32_t sa = smb + s * STAGE_BYTES;
        const uint32_t sb = sa + 16384;
#pragma unroll
        for (int kk = 0; kk < 4; kk++) {
            uint32_t af[2][4];
#pragma unroll
            for (int mi = 0; mi < 2; mi++) {
                int row = a_row + mi * 16;
                int cc = kk * 2 + a_ccb;
                ldsm4(af[mi], sa + row * 128 + ((cc ^ (row & 7)) << 4));
            }
#pragma unroll
            for (int nj = 0; nj < 4; nj++) {
                uint32_t bf[4];
                int row = b_row + nj * 16;
                int cc = kk * 2 + b_ccb;
                ldsm4(bf, sb + row * 128 + ((cc ^ (row & 7)) << 4));
#pragma unroll
                for (int mi = 0; mi < 2; mi++) {
                    mma16816(acc[mi][nj * 2],     af[mi], bf[0], bf[1]);
                    mma16816(acc[mi][nj * 2 + 1], af[mi], bf[2], bf[3]);
                }
            }
        }
    }

    const int g = lane >> 2, t = lane & 3;
#pragma unroll
    for (int mi = 0; mi < 2; mi++) {
#pragma unroll
        for (int ni = 0; ni < 8; ni++) {
            const int col = bx * 128 + n0w + ni * 8 + 2 * t;
            const float b0 = __ldg(bias + col);
            const float b1 = __ldg(bias + col + 1);
            const int row0 = by * 128 + m0w + mi * 16 + g;
#pragma unroll
            for (int h = 0; h < 2; h++) {
                const int row = row0 + h * 8;
                float v0 = acc[mi][ni][2 * h]     + b0;
                float v1 = acc[mi][ni][2 * h + 1] + b1;
                if (MODE == 2) {
                    v0 = gelu_exact(v0); v1 = gelu_exact(v1);
                    *(uint32_t*)(Cb + (size_t)row * KOUT + col) = pack_h2(v0, v1);
                } else if (MODE == 4) {
                    *(uint32_t*)(Cb + (size_t)row * KOUT + col) = pack_h2(v0, v1);
                } else {
                    const size_t base = (size_t)row * Nn + col;
                    if (MODE == 3) {
                        v0 += res1[base]     + res2[base];
                        v1 += res1[base + 1] + res2[base + 1];
                    }
                    *(float2*)(Cf + base) = make_float2(v0, v1);
                }
            }
        }
    }
}

// ---------------- merged prep kernel -------------------------------------------
#define TB_WQ   1024
#define TB_WK   768
#define TB_WV   768
#define TB_WO   1024
#define TB_W1   4096
#define TB_W2   4096
#define CB_X    8192
#define CB_XF   384
#define PREP_BLOCKS (TB_WQ+TB_WK+TB_WV+TB_WO+TB_W1+TB_W2+CB_X+CB_XF+1)

__device__ __forceinline__ void trans_tile(
    const float* __restrict__ W, __half* __restrict__ Y,
    int K, int N, int rowOff, int tileIdx, int tid)
{
    __shared__ float tile[32][33];
    const int nt = N >> 5;
    const int bx = tileIdx % nt, by = tileIdx / nt;
    const int n0 = bx * 32, k0 = by * 32;
    const int tx = tid & 31, ty = tid >> 5;
#pragma unroll
    for (int j = 0; j < 4; j++)
        tile[ty + j * 8][tx] = W[(size_t)(k0 + ty + j * 8) * N + n0 + tx];
    __syncthreads();
#pragma unroll
    for (int j = 0; j < 4; j++)
        Y[(size_t)(rowOff + n0 + ty + j * 8) * K + k0 + tx] =
            __float2half_rn(tile[tx][ty + j * 8]);
}

__device__ __forceinline__ void conv_seg(
    const float* __restrict__ X, __half* __restrict__ Y, int segIdx, int tid)
{
    size_t base = (size_t)segIdx * 2048 + tid * 8;
    float4 a = *(const float4*)(X + base);
    float4 b = *(const float4*)(X + base + 4);
    *(uint4*)(Y + base) = make_uint4(pack_h2(a.x, a.y), pack_h2(a.z, a.w),
                                    pack_h2(b.x, b.y), pack_h2(b.z, b.w));
}

__global__ void __launch_bounds__(256) prep_kernel(
    const float* __restrict__ Wq, const float* __restrict__ Wk,
    const float* __restrict__ Wv, const float* __restrict__ Wo,
    const float* __restrict__ W1, const float* __restrict__ W2,
    const float* __restrict__ x,  const float* __restrict__ xf,
    const float* __restrict__ bk, const float* __restrict__ bv,
    __half* __restrict__ wq, __half* __restrict__ wkv, __half* __restrict__ wo,
    __half* __restrict__ w1, __half* __restrict__ w2,
    __half* __restrict__ xs, __half* __restrict__ xfs, float* __restrict__ bkv)
{
    int b = blockIdx.x;
    const int tid = threadIdx.x;
    if (b < TB_WQ)  { trans_tile(Wq, wq,  DMODEL, DMODEL, 0,      b, tid); return; }
    b -= TB_WQ;
    if (b < TB_WK)  { trans_tile(Wk, wkv, DTEXT,  DMODEL, 0,      b, tid); return; }
    b -= TB_WK;
    if (b < TB_WV)  { trans_tile(Wv, wkv, DTEXT,  DMODEL, DMODEL, b, tid); return; }
    b -= TB_WV;
    if (b < TB_WO)  { trans_tile(Wo, wo,  DMODEL, DMODEL, 0,      b, tid); return; }
    b -= TB_WO;
    if (b < TB_W1)  { trans_tile(W1, w1,  DMODEL, DFF,    0,      b, tid); return; }
    b -= TB_W1;
    if (b < TB_W2)  { trans_tile(W2, w2,  DFF,    DMODEL, 0,      b, tid); return; }
    b -= TB_W2;
    if (b < CB_X)   { conv_seg(x,  xs,  b, tid); return; }
    b -= CB_X;
    if (b < CB_XF)  { conv_seg(xf, xfs, b, tid); return; }
    for (int i = tid; i < DMODEL; i += 256) {
        bkv[i] = bk[i]; bkv[DMODEL + i] = bv[i];
    }
}

// ---------------- HMMA flash-attention -----------------------------------------
#define AQT 128
#define KVW (2 * DMODEL)

__global__ void __launch_bounds__(256, 2) attn_kernel(
    const __half* __restrict__ Qh, const __half* __restrict__ KVh,
    __half* __restrict__ O)
{
    extern __shared__ char smraw[];
    const uint32_t smb = smem_u32(smraw);
    const uint32_t sQ = smb;
    const uint32_t sK = smb + 16384;
    const uint32_t sV = smb + 49152;

    const int bid   = blockIdx.x;
    const int chunk = bid & 31;
    const int h     = (bid >> 5) & 15;
    const int b     = bid >> 9;

    const int tid  = threadIdx.x;
    const int lane = tid & 31;
    const int w    = tid >> 5;

    {
        const __half* qg = Qh + (size_t)(b * TXQ + chunk * AQT) * DMODEL + h * HDIM;
        const __half* kg = KVh + (size_t)(b * TXFK) * KVW + h * HDIM;
        const __half* vg = kg + DMODEL;
#pragma unroll
        for (int i = 0; i < 4; i++) {
            int idx = tid + i * 256;
            int row = idx >> 3, cc = idx & 7;
            uint32_t off = row * 128 + ((cc ^ (row & 7)) << 4);
            cp16(sQ + off, qg + (size_t)row * DMODEL + cc * 8);
        }
#pragma unroll
        for (int i = 0; i < 8; i++) {
            int idx = tid + i * 256;
            int row = idx >> 3, cc = idx & 7;
            uint32_t off = row * 128 + ((cc ^ (row & 7)) << 4);
            cp16(sK + off, kg + (size_t)row * KVW + cc * 8);
        }
        asm volatile("cp.async.commit_group;" ::: "memory");
#pragma unroll
        for (int i = 0; i < 8; i++) {
            int idx = tid + i * 256;
            int row = idx >> 3, cc = idx & 7;
            uint32_t off = row * 128 + ((cc ^ (row & 7)) << 4);
            cp16(sV + off, vg + (size_t)row * KVW + cc * 8);
        }
        asm volatile("cp.async.commit_group;" ::: "memory");
        asm volatile("cp.async.wait_group 1;" ::: "memory");
        __syncthreads();
    }

    uint32_t qf[4][4];
#pragma unroll
    for (int s = 0; s < 4; s++) {
        int row = w * 16 + (lane & 15);
        int cc = 2 * s + (lane >> 4);
        ldsm4(qf[s], sQ + row * 128 + ((cc ^ (row & 7)) << 4));
    }

    float oacc[8][4];
#pragma unroll
    for (int j = 0; j < 8; j++)
#pragma unroll
        for (int q = 0; q < 4; q++) oacc[j][q] = 0.0f;
    float m = -1e30f, l0 = 0.0f, l1 = 0.0f;

    for (int c = 0; c < 4; c++) {
        const int kb = c * 64;
        float sacc[8][4];
#pragma unroll
        for (int j = 0; j < 8; j++)
#pragma unroll
            for (int q = 0; q < 4; q++) sacc[j][q] = 0.0f;

#pragma unroll
        for (int s = 0; s < 4; s++) {
#pragma unroll
            for (int njp = 0; njp < 4; njp++) {
                uint32_t kf[4];
                int row = kb + njp * 16 + (lane & 7) + ((lane >> 4) << 3);
                int cc = 2 * s + ((lane >> 3) & 1);
                ldsm4(kf, sK + row * 128 + ((cc ^ (row & 7)) << 4));
                mma16816(sacc[njp * 2],     qf[s], kf[0], kf[1]);
                mma16816(sacc[njp * 2 + 1], qf[s], kf[2], kf[3]);
            }
        }

        float mx = -1e30f;
#pragma unroll
        for (int j = 0; j < 8; j++) {
            mx = fmaxf(mx, fmaxf(fmaxf(sacc[j][0], sacc[j][1]),
                                 fmaxf(sacc[j][2], sacc[j][3])));
        }
        mx = fmaxf(mx, __shfl_xor_sync(~0u, mx, 1));
        mx = fmaxf(mx, __shfl_xor_sync(~0u, mx, 2));
        float mn = fmaxf(m, mx * SCALE_LOG2E);
        float sc = fexp2(m - mn);
        m = mn;

        float rs0 = 0.0f, rs1 = 0.0f;
#pragma unroll
        for (int j = 0; j < 8; j++) {
            sacc[j][0] = fexp2(fmaf(sacc[j][0], SCALE_LOG2E, -m));
            sacc[j][1] = fexp2(fmaf(sacc[j][1], SCALE_LOG2E, -m));
            sacc[j][2] = fexp2(fmaf(sacc[j][2], SCALE_LOG2E, -m));
            sacc[j][3] = fexp2(fmaf(sacc[j][3], SCALE_LOG2E, -m));
            rs0 += sacc[j][0] + sacc[j][1];
            rs1 += sacc[j][2] + sacc[j][3];
        }
        rs0 += __shfl_xor_sync(~0u, rs0, 1);
        rs0 += __shfl_xor_sync(~0u, rs0, 2);
        rs1 += __shfl_xor_sync(~0u, rs1, 1);
        rs1 += __shfl_xor_sync(~0u, rs1, 2);
        l0 = l0 * sc + rs0;
        l1 = l1 * sc + rs1;
#pragma unroll
        for (int j = 0; j < 8; j++) {
            oacc[j][0] *= sc; oacc[j][1] *= sc;
            oacc[j][2] *= sc; oacc[j][3] *= sc;
        }

        if (c == 0) {
            asm volatile("cp.async.wait_group 0;" ::: "memory");
            __syncthreads();
        }

#pragma unroll
        for (int t2 = 0; t2 < 4; t2++) {
            uint32_t pf[4];
            pf[0] = pack_h2(sacc[2 * t2][0],     sacc[2 * t2][1]);
            pf[1] = pack_h2(sacc[2 * t2][2],     sacc[2 * t2][3]);
            pf[2] = pack_h2(sacc[2 * t2 + 1][0], sacc[2 * t2 + 1][1]);
            pf[3] = pack_h2(sacc[2 * t2 + 1][2], sacc[2 * t2 + 1][3]);
            const int kk = kb + t2 * 16;
#pragma unroll
            for (int ndp = 0; ndp < 4; ndp++) {
                uint32_t vf[4];
                int row = kk + ((lane >> 3) & 1) * 8 + (lane & 7);
                int cc = 2 * ndp + (lane >> 4);
                ldsm4t(vf, sV + row * 128 + ((cc ^ (row & 7)) << 4));
                mma16816(oacc[ndp * 2],     pf, vf[0], vf[1]);
                mma16816(oacc[ndp * 2 + 1], pf, vf[2], vf[3]);
            }
        }
    }

    const float inv0 = 1.0f / l0, inv1 = 1.0f / l1;
    const int g = lane >> 2, t = lane & 3;
    const size_t row0 = (size_t)(b * TXQ + chunk * AQT + w * 16 + g);
#pragma unroll
    for (int j = 0; j < 8; j++) {
        int col = h * HDIM + j * 8 + 2 * t;
        *(uint32_t*)(O + row0 * DMODEL + col) =
            pack_h2(oacc[j][0] * inv0, oacc[j][1] * inv0);
        *(uint32_t*)(O + (row0 + 8) * DMODEL + col) =
            pack_h2(oacc[j][2] * inv1, oacc[j][3] * inv1);
    }
}

// ---------------- LayerNorm -> fp16 --------------------------------------------
__global__ void __launch_bounds__(256) ln_conv_kernel(
    const float* __restrict__ X, const float* __restrict__ gw,
    const float* __restrict__ bw, __half* __restrict__ Y)
{
    const int row = blockIdx.x;
    const int t = threadIdx.x;
    float4 v = ((const float4*)(X + (size_t)row * DMODEL))[t];
    float s1 = v.x + v.y + v.z + v.w;
    float s2 = v.x * v.x + v.y * v.y + v.z * v.z + v.w * v.w;
#pragma unroll
    for (int o = 16; o; o >>= 1) {
        s1 += __shfl_xor_sync(~0u, s1, o);
        s2 += __shfl_xor_sync(~0u, s2, o);
    }
    __shared__ float r1[8], r2[8];
    const int w = t >> 5, lane = t & 31;
    if (lane == 0) { r1[w] = s1; r2[w] = s2; }
    __syncthreads();
    if (w == 0) {
        s1 = (lane < 8) ? r1[lane] : 0.0f;
        s2 = (lane < 8) ? r2[lane] : 0.0f;
#pragma unroll
        for (int o = 4; o; o >>= 1) {
            s1 += __shfl_xor_sync(~0u, s1, o);
            s2 += __shfl_xor_sync(~0u, s2, o);
        }
        if (lane == 0) { r1[0] = s1; r2[0] = s2; }
    }
    __syncthreads();
    const float mean = r1[0] * (1.0f / DMODEL);
    const float var  = r2[0] * (1.0f / DMODEL) - mean * mean;
    const float rstd = rsqrtf(var + 1e-5f);
    float4 g4 = ((const float4*)gw)[t];
    float4 b4 = ((const float4*)bw)[t];
    float vv[4];
    vv[0] = (v.x - mean) * rstd * g4.x + b4.x;
    vv[1] = (v.y - mean) * rstd * g4.y + b4.y;
    vv[2] = (v.z - mean) * rstd * g4.z + b4.z;
    vv[3] = (v.w - mean) * rstd * g4.w + b4.w;

    *(uint2*)(Y + (size_t)row * DMODEL + t * 4) =
        make_uint2(pack_h2(vv[0], vv[1]), pack_h2(vv[2], vv[3]));
}

// ---------------- launch -------------------------------------------------------
extern "C" void kernel_launch(void* const* d_in, const int* in_sizes, int n_in,
                              void* d_out, int out_size)
{
    const float* x    = (const float*)d_in[0];
    const float* xf   = (const float*)d_in[1];
    const float* Wq   = (const float*)d_in[2];
    const float* bq   = (const float*)d_in[3];
    const float* Wk   = (const float*)d_in[4];
    const float* bk   = (const float*)d_in[5];
    const float* Wv   = (const float*)d_in[6];
    const float* bv   = (const float*)d_in[7];
    const float* Wo   = (const float*)d_in[8];
    const float* bo   = (const float*)d_in[9];
    const float* ln_g = (const float*)d_in[10];
    const float* ln_b = (const float*)d_in[11];
    const float* W1   = (const float*)d_in[12];
    const float* b1   = (const float*)d_in[13];
    const float* W2   = (const float*)d_in[14];
    const float* b2   = (const float*)d_in[15];
    float* out = (float*)d_out;

    float *res, *bkv;
    __half *xs, *xfs, *qh, *kvh, *attns, *lns, *hs, *wq, *wkv, *wo, *w1, *w2;
    cudaGetSymbolAddress((void**)&res,   g_res);
    cudaGetSymbolAddress((void**)&bkv,   g_bkv);
    cudaGetSymbolAddress((void**)&xs,    g_xs);
    cudaGetSymbolAddress((void**)&xfs,   g_xfs);
    cudaGetSymbolAddress((void**)&qh,    g_qh);
    cudaGetSymbolAddress((void**)&kvh,   g_kvh);
    cudaGetSymbolAddress((void**)&attns, g_attns);
    cudaGetSymbolAddress((void**)&lns,   g_lns);
    cudaGetSymbolAddress((void**)&hs,    g_hs);
    cudaGetSymbolAddress((void**)&wq,    g_wq);
    cudaGetSymbolAddress((void**)&wkv,   g_wkv);
    cudaGetSymbolAddress((void**)&wo,    g_wo);
    cudaGetSymbolAddress((void**)&w1,    g_w1);
    cudaGetSymbolAddress((void**)&w2,    g_w2);

    const int GEMM_SMEM = NSTAGE * STAGE_BYTES;   // 96KB
    cudaFuncSetAttribute(mma_gemm<0>, cudaFuncAttributeMaxDynamicSharedMemorySize, GEMM_SMEM);
    cudaFuncSetAttribute(mma_gemm<2>, cudaFuncAttributeMaxDynamicSharedMemorySize, GEMM_SMEM);
    cudaFuncSetAttribute(mma_gemm<3>, cudaFuncAttributeMaxDynamicSharedMemorySize, GEMM_SMEM);
    cudaFuncSetAttribute(mma_gemm<4>, cudaFuncAttributeMaxDynamicSharedMemorySize, GEMM_SMEM);
    const int ATTN_SMEM = 81920;
    cudaFuncSetAttribute(attn_kernel, cudaFuncAttributeMaxDynamicSharedMemorySize, ATTN_SMEM);

    dim3 blk(256);

    // side stream + events for independent KV projection (graph-capturable fork/join)
    static cudaStream_t s1 = nullptr;
    static cudaEvent_t evFork = nullptr, evJoin = nullptr;
    if (!s1) {
        cudaStreamCreateWithFlags(&s1, cudaStreamNonBlocking);
        cudaEventCreateWithFlags(&evFork, cudaEventDisableTiming);
        cudaEventCreateWithFlags(&evJoin, cudaEventDisableTiming);
    }

    // ONE merged prep launch
    prep_kernel<<<PREP_BLOCKS, blk>>>(Wq, Wk, Wv, Wo, W1, W2, x, xf, bk, bv,
                                      wq, wkv, wo, w1, w2, xs, xfs, bkv);

    // fork: KV projection on side stream, Q projection on main stream
    cudaEventRecord(evFork, 0);
    cudaStreamWaitEvent(s1, evFork, 0);
    mma_gemm<4><<<dim3(2 * DMODEL / 128, MKV / 128), blk, GEMM_SMEM, s1>>>(
        2 * DMODEL, DTEXT, xfs, wkv, bkv, nullptr, nullptr, nullptr, kvh, 2 * DMODEL);
    cudaEventRecord(evJoin, s1);

    mma_gemm<4><<<dim3(DMODEL / 128, MQ / 128), blk, GEMM_SMEM>>>(
        DMODEL, DMODEL, xs, wq, bq, nullptr, nullptr, nullptr, qh, DMODEL);

    // join: attention needs both Q and KV
    cudaStreamWaitEvent(0, evJoin, 0);
    attn_kernel<<<BDIM * NHEADS * (TXQ / AQT), blk, ATTN_SMEM>>>(qh, kvh, attns);

    // out = attn@Wo + bo
    mma_gemm<0><<<dim3(DMODEL / 128, MQ / 128), blk, GEMM_SMEM>>>(
        DMODEL, DMODEL, attns, wo, bo, nullptr, nullptr, res, nullptr, 0);

    // LayerNorm -> fp16
    ln_conv_kernel<<<MQ, blk>>>(res, ln_g, ln_b, lns);

    // h = GELU(ln@W1 + b1)
    mma_gemm<2><<<dim3(DFF / 128, MQ / 128), blk, GEMM_SMEM>>>(
        DFF, DMODEL, lns, w1, b1, nullptr, nullptr, nullptr, hs, DFF);

    // final = h@W2 + b2 + res + x
    mma_gemm<3><<<dim3(DMODEL / 128, MQ / 128), blk, GEMM_SMEM>>>(
        DMODEL, DFF, hs, w2, b2, res, x, out, nullptr, 0);
}

// round 17
// speedup vs baseline: 1.0888x; 1.0044x over previous
#include <cuda_runtime.h>
#include <cuda_fp16.h>
#include <math.h>
#include <stdint.h>

#define BDIM   4
#define TXQ    4096
#define TXFK   256
#define DMODEL 1024
#define DTEXT  768
#define NHEADS 16
#define HDIM   64
#define MQ     (BDIM*TXQ)     // 16384
#define MKV    (BDIM*TXFK)    // 1024
#define DFF    4096
#define ATT_SCALE 0.125f
#define SCALE_LOG2E 0.1803368801111906f

// ---------------- scratch (device globals) -----------------------------------
__device__ float g_res [(size_t)MQ * DMODEL];
__device__ float g_bkv [2 * DMODEL];

__device__ __half g_xs   [(size_t)MQ  * DMODEL];
__device__ __half g_xfs  [(size_t)MKV * DTEXT];
__device__ __half g_qh   [(size_t)MQ  * DMODEL];
__device__ __half g_kvh  [(size_t)MKV * 2 * DMODEL];
__device__ __half g_attns[(size_t)MQ  * DMODEL];
__device__ __half g_lns  [(size_t)MQ  * DMODEL];
__device__ __half g_hs   [(size_t)MQ  * DFF];
__device__ __half g_wq   [(size_t)DMODEL * DMODEL];
__device__ __half g_wkv  [(size_t)2 * DMODEL * DTEXT];
__device__ __half g_wo   [(size_t)DMODEL * DMODEL];
__device__ __half g_w1   [(size_t)DFF    * DMODEL];
__device__ __half g_w2   [(size_t)DMODEL * DFF];

__device__ __forceinline__ float gelu_exact(float v) {
    return 0.5f * v * (1.0f + erff(v * 0.7071067811865476f));
}

// ---------------- PTX helpers (target-portable, sm_80+) -----------------------
__device__ __forceinline__ uint32_t smem_u32(const void* p) {
    uint32_t a;
    asm("{ .reg .u64 t; cvta.to.shared.u64 t, %1; cvt.u32.u64 %0, t; }"
        : "=r"(a) : "l"(p));
    return a;
}
__device__ __forceinline__ void cp16(uint32_t s, const void* g) {
    asm volatile("cp.async.cg.shared.global [%0], [%1], 16;" :: "r"(s), "l"(g));
}
__device__ __forceinline__ void ldsm4(uint32_t* r, uint32_t a) {
    asm volatile("ldmatrix.sync.aligned.m8n8.x4.shared.b16 {%0,%1,%2,%3}, [%4];"
        : "=r"(r[0]), "=r"(r[1]), "=r"(r[2]), "=r"(r[3]) : "r"(a));
}
__device__ __forceinline__ void ldsm4t(uint32_t* r, uint32_t a) {
    asm volatile("ldmatrix.sync.aligned.m8n8.x4.trans.shared.b16 {%0,%1,%2,%3}, [%4];"
        : "=r"(r[0]), "=r"(r[1]), "=r"(r[2]), "=r"(r[3]) : "r"(a));
}
__device__ __forceinline__ void mma16816(float* c, const uint32_t* a,
                                         uint32_t b0, uint32_t b1) {
    asm volatile(
        "mma.sync.aligned.m16n8k16.row.col.f32.f16.f16.f32 "
        "{%0,%1,%2,%3}, {%4,%5,%6,%7}, {%8,%9}, {%0,%1,%2,%3};"
        : "+f"(c[0]), "+f"(c[1]), "+f"(c[2]), "+f"(c[3])
        : "r"(a[0]), "r"(a[1]), "r"(a[2]), "r"(a[3]), "r"(b0), "r"(b1));
}
__device__ __forceinline__ uint32_t pack_h2(float a, float b) {
    __half2 t = __floats2half2_rn(a, b);
    uint32_t u; memcpy(&u, &t, 4); return u;
}
__device__ __forceinline__ float fexp2(float y) {
    y = fmaxf(y, -80.0f);
    float r = rintf(y);
    float f = y - r;
    float p =          1.3333558e-3f;
    p = fmaf(p, f,     9.6181291e-3f);
    p = fmaf(p, f,     5.5504109e-2f);
    p = fmaf(p, f,     2.4022651e-1f);
    p = fmaf(p, f,     6.9314718e-1f);
    p = fmaf(p, f,     1.0f);
    return __int_as_float(__float_as_int(p) + (((int)r) << 23));
}

// ---------------- pure fp16 HMMA GEMM (BM=BN=128, BK=64) -----------------------
// Inner loop restructured: all 6 ldsm4 issued up front per kk (independent),
// then 16 MMAs — breaks ldsm->mma serial latency chains.
#define STAGE_BYTES 32768
#define NSTAGE 3
#define RASTER_G 16

template<int MODE>
__global__ void __launch_bounds__(256, 2) mma_gemm(
    int Nn, int Kk,
    const __half* __restrict__ A, const __half* __restrict__ Bw,
    const float* __restrict__ bias,
    const float* __restrict__ res1, const float* __restrict__ res2,
    float* __restrict__ Cf, __half* __restrict__ Cb, int KOUT)
{
    extern __shared__ char smraw[];
    const uint32_t smb = smem_u32(smraw);

    const int tid = threadIdx.x;
    const int numX = gridDim.x, numY = gridDim.y;
    const int bid = blockIdx.y * numX + blockIdx.x;
    const int strip = RASTER_G * numX;
    const int sIdx = bid / strip;
    const int rIdx = bid % strip;
    const int gRows = (numY - sIdx * RASTER_G) < RASTER_G ? (numY - sIdx * RASTER_G)
                                                          : RASTER_G;
    const int by = sIdx * RASTER_G + (rIdx % gRows);
    const int bx = rIdx / gRows;

    const int w = tid >> 5, lane = tid & 31;
    const int m0w = (w & 3) * 32, n0w = (w >> 2) * 64;

    const __half* Abase = A  + (size_t)(by * 128) * Kk;
    const __half* Bbase = Bw + (size_t)(bx * 128) * Kk;
    const int nch = Kk >> 6;

    auto load_stage = [&](int c, int s) {
        const uint32_t sa = smb + s * STAGE_BYTES;
        const uint32_t sb = sa + 16384;
        const int k0 = c * 64;
#pragma unroll
        for (int i = 0; i < 4; i++) {
            int idx = tid + i * 256;
            int row = idx >> 3, cc = idx & 7;
            uint32_t off = row * 128 + ((cc ^ (row & 7)) << 4);
            cp16(sa + off, Abase + (size_t)row * Kk + k0 + cc * 8);
            cp16(sb + off, Bbase + (size_t)row * Kk + k0 + cc * 8);
        }
        asm volatile("cp.async.commit_group;" ::: "memory");
    };

    float acc[2][8][4];
#pragma unroll
    for (int i = 0; i < 2; i++)
#pragma unroll
        for (int j = 0; j < 8; j++)
#pragma unroll
            for (int q = 0; q < 4; q++) acc[i][j][q] = 0.0f;

    const int a_row = m0w + (lane & 15);
    const int a_ccb = lane >> 4;
    const int b_row = n0w + (lane & 7) + ((lane >> 4) << 3);
    const int b_ccb = (lane >> 3) & 1;

    load_stage(0, 0);
    if (nch > 1) load_stage(1, 1);

    for (int c = 0; c < nch; c++) {
        const int s = c % NSTAGE;
        if (c + 1 < nch) asm volatile("cp.async.wait_group 1;" ::: "memory");
        else             asm volatile("cp.async.wait_group 0;" ::: "memory");
        __syncthreads();
        if (c + 2 < nch) load_stage(c + 2, (c + 2) % NSTAGE);

        const uint32_t sa = smb + s * STAGE_BYTES;
        const uint32_t sb = sa + 16384;
#pragma unroll
        for (int kk = 0; kk < 4; kk++) {
            uint32_t af[2][4], bf[4][4];
            // issue ALL fragment loads first (independent ldsm4s pipeline in LSU)
#pragma unroll
            for (int mi = 0; mi < 2; mi++) {
                int row = a_row + mi * 16;
                int cc = kk * 2 + a_ccb;
                ldsm4(af[mi], sa + row * 128 + ((cc ^ (row & 7)) << 4));
            }
#pragma unroll
            for (int nj = 0; nj < 4; nj++) {
                int row = b_row + nj * 16;
                int cc = kk * 2 + b_ccb;
                ldsm4(bf[nj], sb + row * 128 + ((cc ^ (row & 7)) << 4));
            }
            // then all 16 MMAs
#pragma unroll
            for (int nj = 0; nj < 4; nj++) {
#pragma unroll
                for (int mi = 0; mi < 2; mi++) {
                    mma16816(acc[mi][nj * 2],     af[mi], bf[nj][0], bf[nj][1]);
                    mma16816(acc[mi][nj * 2 + 1], af[mi], bf[nj][2], bf[nj][3]);
                }
            }
        }
    }

    const int g = lane >> 2, t = lane & 3;
#pragma unroll
    for (int mi = 0; mi < 2; mi++) {
#pragma unroll
        for (int ni = 0; ni < 8; ni++) {
            const int col = bx * 128 + n0w + ni * 8 + 2 * t;
            const float b0 = __ldg(bias + col);
            const float b1 = __ldg(bias + col + 1);
            const int row0 = by * 128 + m0w + mi * 16 + g;
#pragma unroll
            for (int h = 0; h < 2; h++) {
                const int row = row0 + h * 8;
                float v0 = acc[mi][ni][2 * h]     + b0;
                float v1 = acc[mi][ni][2 * h + 1] + b1;
                if (MODE == 2) {
                    v0 = gelu_exact(v0); v1 = gelu_exact(v1);
                    *(uint32_t*)(Cb + (size_t)row * KOUT + col) = pack_h2(v0, v1);
                } else if (MODE == 4) {
                    *(uint32_t*)(Cb + (size_t)row * KOUT + col) = pack_h2(v0, v1);
                } else {
                    const size_t base = (size_t)row * Nn + col;
                    if (MODE == 3) {
                        v0 += res1[base]     + res2[base];
                        v1 += res1[base + 1] + res2[base + 1];
                    }
                    *(float2*)(Cf + base) = make_float2(v0, v1);
                }
            }
        }
    }
}

// ---------------- merged prep kernel -------------------------------------------
#define TB_WQ   1024
#define TB_WK   768
#define TB_WV   768
#define TB_WO   1024
#define TB_W1   4096
#define TB_W2   4096
#define CB_X    8192
#define CB_XF   384
#define PREP_BLOCKS (TB_WQ+TB_WK+TB_WV+TB_WO+TB_W1+TB_W2+CB_X+CB_XF+1)

__device__ __forceinline__ void trans_tile(
    const float* __restrict__ W, __half* __restrict__ Y,
    int K, int N, int rowOff, int tileIdx, int tid)
{
    __shared__ float tile[32][33];
    const int nt = N >> 5;
    const int bx = tileIdx % nt, by = tileIdx / nt;
    const int n0 = bx * 32, k0 = by * 32;
    const int tx = tid & 31, ty = tid >> 5;
#pragma unroll
    for (int j = 0; j < 4; j++)
        tile[ty + j * 8][tx] = W[(size_t)(k0 + ty + j * 8) * N + n0 + tx];
    __syncthreads();
#pragma unroll
    for (int j = 0; j < 4; j++)
        Y[(size_t)(rowOff + n0 + ty + j * 8) * K + k0 + tx] =
            __float2half_rn(tile[tx][ty + j * 8]);
}

__device__ __forceinline__ void conv_seg(
    const float* __restrict__ X, __half* __restrict__ Y, int segIdx, int tid)
{
    size_t base = (size_t)segIdx * 2048 + tid * 8;
    float4 a = *(const float4*)(X + base);
    float4 b = *(const float4*)(X + base + 4);
    *(uint4*)(Y + base) = make_uint4(pack_h2(a.x, a.y), pack_h2(a.z, a.w),
                                    pack_h2(b.x, b.y), pack_h2(b.z, b.w));
}

__global__ void __launch_bounds__(256) prep_kernel(
    const float* __restrict__ Wq, const float* __restrict__ Wk,
    const float* __restrict__ Wv, const float* __restrict__ Wo,
    const float* __restrict__ W1, const float* __restrict__ W2,
    const float* __restrict__ x,  const float* __restrict__ xf,
    const float* __restrict__ bk, const float* __restrict__ bv,
    __half* __restrict__ wq, __half* __restrict__ wkv, __half* __restrict__ wo,
    __half* __restrict__ w1, __half* __restrict__ w2,
    __half* __restrict__ xs, __half* __restrict__ xfs, float* __restrict__ bkv)
{
    int b = blockIdx.x;
    const int tid = threadIdx.x;
    if (b < TB_WQ)  { trans_tile(Wq, wq,  DMODEL, DMODEL, 0,      b, tid); return; }
    b -= TB_WQ;
    if (b < TB_WK)  { trans_tile(Wk, wkv, DTEXT,  DMODEL, 0,      b, tid); return; }
    b -= TB_WK;
    if (b < TB_WV)  { trans_tile(Wv, wkv, DTEXT,  DMODEL, DMODEL, b, tid); return; }
    b -= TB_WV;
    if (b < TB_WO)  { trans_tile(Wo, wo,  DMODEL, DMODEL, 0,      b, tid); return; }
    b -= TB_WO;
    if (b < TB_W1)  { trans_tile(W1, w1,  DMODEL, DFF,    0,      b, tid); return; }
    b -= TB_W1;
    if (b < TB_W2)  { trans_tile(W2, w2,  DFF,    DMODEL, 0,      b, tid); return; }
    b -= TB_W2;
    if (b < CB_X)   { conv_seg(x,  xs,  b, tid); return; }
    b -= CB_X;
    if (b < CB_XF)  { conv_seg(xf, xfs, b, tid); return; }
    for (int i = tid; i < DMODEL; i += 256) {
        bkv[i] = bk[i]; bkv[DMODEL + i] = bv[i];
    }
}

// ---------------- HMMA flash-attention -----------------------------------------
#define AQT 128
#define KVW (2 * DMODEL)

__global__ void __launch_bounds__(256, 2) attn_kernel(
    const __half* __restrict__ Qh, const __half* __restrict__ KVh,
    __half* __restrict__ O)
{
    extern __shared__ char smraw[];
    const uint32_t smb = smem_u32(smraw);
    const uint32_t sQ = smb;
    const uint32_t sK = smb + 16384;
    const uint32_t sV = smb + 49152;

    const int bid   = blockIdx.x;
    const int chunk = bid & 31;
    const int h     = (bid >> 5) & 15;
    const int b     = bid >> 9;

    const int tid  = threadIdx.x;
    const int lane = tid & 31;
    const int w    = tid >> 5;

    {
        const __half* qg = Qh + (size_t)(b * TXQ + chunk * AQT) * DMODEL + h * HDIM;
        const __half* kg = KVh + (size_t)(b * TXFK) * KVW + h * HDIM;
        const __half* vg = kg + DMODEL;
#pragma unroll
        for (int i = 0; i < 4; i++) {
            int idx = tid + i * 256;
            int row = idx >> 3, cc = idx & 7;
            uint32_t off = row * 128 + ((cc ^ (row & 7)) << 4);
            cp16(sQ + off, qg + (size_t)row * DMODEL + cc * 8);
        }
#pragma unroll
        for (int i = 0; i < 8; i++) {
            int idx = tid + i * 256;
            int row = idx >> 3, cc = idx & 7;
            uint32_t off = row * 128 + ((cc ^ (row & 7)) << 4);
            cp16(sK + off, kg + (size_t)row * KVW + cc * 8);
        }
        asm volatile("cp.async.commit_group;" ::: "memory");
#pragma unroll
        for (int i = 0; i < 8; i++) {
            int idx = tid + i * 256;
            int row = idx >> 3, cc = idx & 7;
            uint32_t off = row * 128 + ((cc ^ (row & 7)) << 4);
            cp16(sV + off, vg + (size_t)row * KVW + cc * 8);
        }
        asm volatile("cp.async.commit_group;" ::: "memory");
        asm volatile("cp.async.wait_group 1;" ::: "memory");
        __syncthreads();
    }

    uint32_t qf[4][4];
#pragma unroll
    for (int s = 0; s < 4; s++) {
        int row = w * 16 + (lane & 15);
        int cc = 2 * s + (lane >> 4);
        ldsm4(qf[s], sQ + row * 128 + ((cc ^ (row & 7)) << 4));
    }

    float oacc[8][4];
#pragma unroll
    for (int j = 0; j < 8; j++)
#pragma unroll
        for (int q = 0; q < 4; q++) oacc[j][q] = 0.0f;
    float m = -1e30f, l0 = 0.0f, l1 = 0.0f;

    for (int c = 0; c < 4; c++) {
        const int kb = c * 64;
        float sacc[8][4];
#pragma unroll
        for (int j = 0; j < 8; j++)
#pragma unroll
            for (int q = 0; q < 4; q++) sacc[j][q] = 0.0f;

#pragma unroll
        for (int s = 0; s < 4; s++) {
            uint32_t kf[4][4];
#pragma unroll
            for (int njp = 0; njp < 4; njp++) {
                int row = kb + njp * 16 + (lane & 7) + ((lane >> 4) << 3);
                int cc = 2 * s + ((lane >> 3) & 1);
                ldsm4(kf[njp], sK + row * 128 + ((cc ^ (row & 7)) << 4));
            }
#pragma unroll
            for (int njp = 0; njp < 4; njp++) {
                mma16816(sacc[njp * 2],     qf[s], kf[njp][0], kf[njp][1]);
                mma16816(sacc[njp * 2 + 1], qf[s], kf[njp][2], kf[njp][3]);
            }
        }

        float mx = -1e30f;
#pragma unroll
        for (int j = 0; j < 8; j++) {
            mx = fmaxf(mx, fmaxf(fmaxf(sacc[j][0], sacc[j][1]),
                                 fmaxf(sacc[j][2], sacc[j][3])));
        }
        mx = fmaxf(mx, __shfl_xor_sync(~0u, mx, 1));
        mx = fmaxf(mx, __shfl_xor_sync(~0u, mx, 2));
        float mn = fmaxf(m, mx * SCALE_LOG2E);
        float sc = fexp2(m - mn);
        m = mn;

        float rs0 = 0.0f, rs1 = 0.0f;
#pragma unroll
        for (int j = 0; j < 8; j++) {
            sacc[j][0] = fexp2(fmaf(sacc[j][0], SCALE_LOG2E, -m));
            sacc[j][1] = fexp2(fmaf(sacc[j][1], SCALE_LOG2E, -m));
            sacc[j][2] = fexp2(fmaf(sacc[j][2], SCALE_LOG2E, -m));
            sacc[j][3] = fexp2(fmaf(sacc[j][3], SCALE_LOG2E, -m));
            rs0 += sacc[j][0] + sacc[j][1];
            rs1 += sacc[j][2] + sacc[j][3];
        }
        rs0 += __shfl_xor_sync(~0u, rs0, 1);
        rs0 += __shfl_xor_sync(~0u, rs0, 2);
        rs1 += __shfl_xor_sync(~0u, rs1, 1);
        rs1 += __shfl_xor_sync(~0u, rs1, 2);
        l0 = l0 * sc + rs0;
        l1 = l1 * sc + rs1;
#pragma unroll
        for (int j = 0; j < 8; j++) {
            oacc[j][0] *= sc; oacc[j][1] *= sc;
            oacc[j][2] *= sc; oacc[j][3] *= sc;
        }

        if (c == 0) {
            asm volatile("cp.async.wait_group 0;" ::: "memory");
            __syncthreads();
        }

#pragma unroll
        for (int t2 = 0; t2 < 4; t2++) {
            uint32_t pf[4];
            pf[0] = pack_h2(sacc[2 * t2][0],     sacc[2 * t2][1]);
            pf[1] = pack_h2(sacc[2 * t2][2],     sacc[2 * t2][3]);
            pf[2] = pack_h2(sacc[2 * t2 + 1][0], sacc[2 * t2 + 1][1]);
            pf[3] = pack_h2(sacc[2 * t2 + 1][2], sacc[2 * t2 + 1][3]);
            const int kk = kb + t2 * 16;
#pragma unroll
            for (int ndp = 0; ndp < 4; ndp++) {
                uint32_t vf[4];
                int row = kk + ((lane >> 3) & 1) * 8 + (lane & 7);
                int cc = 2 * ndp + (lane >> 4);
                ldsm4t(vf, sV + row * 128 + ((cc ^ (row & 7)) << 4));
                mma16816(oacc[ndp * 2],     pf, vf[0], vf[1]);
                mma16816(oacc[ndp * 2 + 1], pf, vf[2], vf[3]);
            }
        }
    }

    const float inv0 = 1.0f / l0, inv1 = 1.0f / l1;
    const int g = lane >> 2, t = lane & 3;
    const size_t row0 = (size_t)(b * TXQ + chunk * AQT + w * 16 + g);
#pragma unroll
    for (int j = 0; j < 8; j++) {
        int col = h * HDIM + j * 8 + 2 * t;
        *(uint32_t*)(O + row0 * DMODEL + col) =
            pack_h2(oacc[j][0] * inv0, oacc[j][1] * inv0);
        *(uint32_t*)(O + (row0 + 8) * DMODEL + col) =
            pack_h2(oacc[j][2] * inv1, oacc[j][3] * inv1);
    }
}

// ---------------- LayerNorm -> fp16 --------------------------------------------
__global__ void __launch_bounds__(256) ln_conv_kernel(
    const float* __restrict__ X, const float* __restrict__ gw,
    const float* __restrict__ bw, __half* __restrict__ Y)
{
    const int row = blockIdx.x;
    const int t = threadIdx.x;
    float4 v = ((const float4*)(X + (size_t)row * DMODEL))[t];
    float s1 = v.x + v.y + v.z + v.w;
    float s2 = v.x * v.x + v.y * v.y + v.z * v.z + v.w * v.w;
#pragma unroll
    for (int o = 16; o; o >>= 1) {
        s1 += __shfl_xor_sync(~0u, s1, o);
        s2 += __shfl_xor_sync(~0u, s2, o);
    }
    __shared__ float r1[8], r2[8];
    const int w = t >> 5, lane = t & 31;
    if (lane == 0) { r1[w] = s1; r2[w] = s2; }
    __syncthreads();
    if (w == 0) {
        s1 = (lane < 8) ? r1[lane] : 0.0f;
        s2 = (lane < 8) ? r2[lane] : 0.0f;
#pragma unroll
        for (int o = 4; o; o >>= 1) {
            s1 += __shfl_xor_sync(~0u, s1, o);
            s2 += __shfl_xor_sync(~0u, s2, o);
        }
        if (lane == 0) { r1[0] = s1; r2[0] = s2; }
    }
    __syncthreads();
    const float mean = r1[0] * (1.0f / DMODEL);
    const float var  = r2[0] * (1.0f / DMODEL) - mean * mean;
    const float rstd = rsqrtf(var + 1e-5f);
    float4 g4 = ((const float4*)gw)[t];
    float4 b4 = ((const float4*)bw)[t];
    float vv[4];
    vv[0] = (v.x - mean) * rstd * g4.x + b4.x;
    vv[1] = (v.y - mean) * rstd * g4.y + b4.y;
    vv[2] = (v.z - mean) * rstd * g4.z + b4.z;
    vv[3] = (v.w - mean) * rstd * g4.w + b4.w;

    *(uint2*)(Y + (size_t)row * DMODEL + t * 4) =
        make_uint2(pack_h2(vv[0], vv[1]), pack_h2(vv[2], vv[3]));
}

// ---------------- launch -------------------------------------------------------
extern "C" void kernel_launch(void* const* d_in, const int* in_sizes, int n_in,
                              void* d_out, int out_size)
{
    const float* x    = (const float*)d_in[0];
    const float* xf   = (const float*)d_in[1];
    const float* Wq   = (const float*)d_in[2];
    const float* bq   = (const float*)d_in[3];
    const float* Wk   = (const float*)d_in[4];
    const float* bk   = (const float*)d_in[5];
    const float* Wv   = (const float*)d_in[6];
    const float* bv   = (const float*)d_in[7];
    const float* Wo   = (const float*)d_in[8];
    const float* bo   = (const float*)d_in[9];
    const float* ln_g = (const float*)d_in[10];
    const float* ln_b = (const float*)d_in[11];
    const float* W1   = (const float*)d_in[12];
    const float* b1   = (const float*)d_in[13];
    const float* W2   = (const float*)d_in[14];
    const float* b2   = (const float*)d_in[15];
    float* out = (float*)d_out;

    float *res, *bkv;
    __half *xs, *xfs, *qh, *kvh, *attns, *lns, *hs, *wq, *wkv, *wo, *w1, *w2;
    cudaGetSymbolAddress((void**)&res,   g_res);
    cudaGetSymbolAddress((void**)&bkv,   g_bkv);
    cudaGetSymbolAddress((void**)&xs,    g_xs);
    cudaGetSymbolAddress((void**)&xfs,   g_xfs);
    cudaGetSymbolAddress((void**)&qh,    g_qh);
    cudaGetSymbolAddress((void**)&kvh,   g_kvh);
    cudaGetSymbolAddress((void**)&attns, g_attns);
    cudaGetSymbolAddress((void**)&lns,   g_lns);
    cudaGetSymbolAddress((void**)&hs,    g_hs);
    cudaGetSymbolAddress((void**)&wq,    g_wq);
    cudaGetSymbolAddress((void**)&wkv,   g_wkv);
    cudaGetSymbolAddress((void**)&wo,    g_wo);
    cudaGetSymbolAddress((void**)&w1,    g_w1);
    cudaGetSymbolAddress((void**)&w2,    g_w2);

    const int GEMM_SMEM = NSTAGE * STAGE_BYTES;   // 96KB
    cudaFuncSetAttribute(mma_gemm<0>, cudaFuncAttributeMaxDynamicSharedMemorySize, GEMM_SMEM);
    cudaFuncSetAttribute(mma_gemm<2>, cudaFuncAttributeMaxDynamicSharedMemorySize, GEMM_SMEM);
    cudaFuncSetAttribute(mma_gemm<3>, cudaFuncAttributeMaxDynamicSharedMemorySize, GEMM_SMEM);
    cudaFuncSetAttribute(mma_gemm<4>, cudaFuncAttributeMaxDynamicSharedMemorySize, GEMM_SMEM);
    const int ATTN_SMEM = 81920;
    cudaFuncSetAttribute(attn_kernel, cudaFuncAttributeMaxDynamicSharedMemorySize, ATTN_SMEM);

    dim3 blk(256);

    static cudaStream_t s1 = nullptr;
    static cudaEvent_t evFork = nullptr, evJoin = nullptr;
    if (!s1) {
        cudaStreamCreateWithFlags(&s1, cudaStreamNonBlocking);
        cudaEventCreateWithFlags(&evFork, cudaEventDisableTiming);
        cudaEventCreateWithFlags(&evJoin, cudaEventDisableTiming);
    }

    // ONE merged prep launch
    prep_kernel<<<PREP_BLOCKS, blk>>>(Wq, Wk, Wv, Wo, W1, W2, x, xf, bk, bv,
                                      wq, wkv, wo, w1, w2, xs, xfs, bkv);

    // fork: KV projection on side stream, Q projection on main stream
    cudaEventRecord(evFork, 0);
    cudaStreamWaitEvent(s1, evFork, 0);
    mma_gemm<4><<<dim3(2 * DMODEL / 128, MKV / 128), blk, GEMM_SMEM, s1>>>(
        2 * DMODEL, DTEXT, xfs, wkv, bkv, nullptr, nullptr, nullptr, kvh, 2 * DMODEL);
    cudaEventRecord(evJoin, s1);

    mma_gemm<4><<<dim3(DMODEL / 128, MQ / 128), blk, GEMM_SMEM>>>(
        DMODEL, DMODEL, xs, wq, bq, nullptr, nullptr, nullptr, qh, DMODEL);

    // join: attention needs both Q and KV
    cudaStreamWaitEvent(0, evJoin, 0);
    attn_kernel<<<BDIM * NHEADS * (TXQ / AQT), blk, ATTN_SMEM>>>(qh, kvh, attns);

    // out = attn@Wo + bo
    mma_gemm<0><<<dim3(DMODEL / 128, MQ / 128), blk, GEMM_SMEM>>>(
        DMODEL, DMODEL, attns, wo, bo, nullptr, nullptr, res, nullptr, 0);

    // LayerNorm -> fp16
    ln_conv_kernel<<<MQ, blk>>>(res, ln_g, ln_b, lns);

    // h = GELU(ln@W1 + b1)
    mma_gemm<2><<<dim3(DFF / 128, MQ / 128), blk, GEMM_SMEM>>>(
        DFF, DMODEL, lns, w1, b1, nullptr, nullptr, nullptr, hs, DFF);

    // final = h@W2 + b2 + res + x
    mma_gemm<3><<<dim3(DMODEL / 128, MQ / 128), blk, GEMM_SMEM>>>(
        DMODEL, DFF, hs, w2, b2, res, x, out, nullptr, 0);
}